// round 12
// baseline (speedup 1.0000x reference)
#include <cuda_runtime.h>
#include <cuda_bf16.h>
#include <math.h>

#define TS   512
#define NB   32
#define DIN  512
#define HID  1024
#define G2   2048

// ---------------- global scratch ----------------
__device__ float    g_XG[(size_t)TS * NB * G2];
__device__ float    g_XC[(size_t)TS * NB * HID];
__device__ unsigned g_h [NB * HID];      // packed bf16 hi|lo<<16
__device__ unsigned g_rh[NB * HID];      // packed
__device__ float    g_u [NB * HID];
__device__ unsigned g_barg[8 * 64];

__global__ void gru_init_kernel() {
    int idx = blockIdx.x * blockDim.x + threadIdx.x;
    if (idx < NB * HID) g_h[idx] = 0u;
    if (idx < 8 * 64) g_barg[idx] = 0u;
}

// ---------------- pack/unpack helpers ----------------
__device__ __forceinline__ unsigned packhl(float v) {
    __nv_bfloat16 hb = __float2bfloat16(v);
    unsigned short hu = *reinterpret_cast<unsigned short*>(&hb);
    float hf = __uint_as_float((unsigned)hu << 16);
    __nv_bfloat16 lb = __float2bfloat16(v - hf);
    unsigned short lu = *reinterpret_cast<unsigned short*>(&lb);
    return (unsigned)hu | ((unsigned)lu << 16);
}
__device__ __forceinline__ float unpackhl(unsigned x) {
    return __uint_as_float(x << 16) + __uint_as_float(x & 0xFFFF0000u);
}

// ---------------- precompute GEMM (unchanged) ----------------
#define BM 128
#define BN 64
#define BK 16
#define APAD 132

__global__ void __launch_bounds__(256) sgemm_bias_kernel(
    const float* __restrict__ A, const float* __restrict__ W,
    const float* __restrict__ bias, float* __restrict__ C,
    int M, int N, int K, int ldw)
{
    __shared__ float As[BK * APAD];
    __shared__ float Ws[BK * BN];

    const int tid = threadIdx.x;
    const int tx = tid & 15;
    const int ty = tid >> 4;
    const int m0 = blockIdx.y * BM;
    const int n0 = blockIdx.x * BN;

    float acc[8][4];
#pragma unroll
    for (int i = 0; i < 8; ++i)
#pragma unroll
        for (int j = 0; j < 4; ++j) acc[i][j] = 0.0f;

    for (int k0 = 0; k0 < K; k0 += BK) {
        {
            const int kq = tid & 3;
            const int mr = tid >> 2;
#pragma unroll
            for (int it = 0; it < 2; ++it) {
                int m = mr + it * 64;
                float4 v = *(const float4*)&A[(size_t)(m0 + m) * K + k0 + kq * 4];
                As[(kq * 4 + 0) * APAD + m] = v.x;
                As[(kq * 4 + 1) * APAD + m] = v.y;
                As[(kq * 4 + 2) * APAD + m] = v.z;
                As[(kq * 4 + 3) * APAD + m] = v.w;
            }
        }
        {
            const int nq = tid & 15;
            const int kr = tid >> 4;
            float4 v = *(const float4*)&W[(size_t)(k0 + kr) * ldw + n0 + nq * 4];
            *(float4*)&Ws[kr * BN + nq * 4] = v;
        }
        __syncthreads();
#pragma unroll
        for (int kk = 0; kk < BK; ++kk) {
            float4 w4 = *(const float4*)&Ws[kk * BN + tx * 4];
            float4 a0 = *(const float4*)&As[kk * APAD + ty * 8];
            float4 a1 = *(const float4*)&As[kk * APAD + ty * 8 + 4];
            float a[8];
            a[0] = a0.x; a[1] = a0.y; a[2] = a0.z; a[3] = a0.w;
            a[4] = a1.x; a[5] = a1.y; a[6] = a1.z; a[7] = a1.w;
#pragma unroll
            for (int i = 0; i < 8; ++i) {
                acc[i][0] += a[i] * w4.x;
                acc[i][1] += a[i] * w4.y;
                acc[i][2] += a[i] * w4.z;
                acc[i][3] += a[i] * w4.w;
            }
        }
        __syncthreads();
    }

    float4 bv = *(const float4*)&bias[n0 + tx * 4];
#pragma unroll
    for (int i = 0; i < 8; ++i) {
        float4 o;
        o.x = acc[i][0] + bv.x;
        o.y = acc[i][1] + bv.y;
        o.z = acc[i][2] + bv.z;
        o.w = acc[i][3] + bv.w;
        *(float4*)&C[(size_t)(m0 + ty * 8 + i) * N + n0 + tx * 4] = o;
    }
}

// ---------------- persistent recurrence (bf16 2-pass mma, direct-LDG A operands) ----------------
#define RBLOCKS  128
#define RTHREADS 256
#define WSTRIDE  1032                // u32 stride per weight j-row (1024 + 8; %32==8)

// smem layout (u32 offsets)
#define OFF_WG   0                   // [16 j][1032 k] packed
#define OFF_WC   16512               // [8 j][1032 k]
#define OFF_RED  24768               // 8 warps x 512 fp32
#define SMEM_U32 28864               // 115456 bytes

__device__ __forceinline__ void mma_bf16(float* c, unsigned a0, unsigned a1,
                                         unsigned a2, unsigned a3,
                                         unsigned b0, unsigned b1) {
    asm("mma.sync.aligned.m16n8k16.row.col.f32.bf16.bf16.f32 "
        "{%0,%1,%2,%3}, {%4,%5,%6,%7}, {%8,%9}, {%0,%1,%2,%3};"
        : "+f"(c[0]), "+f"(c[1]), "+f"(c[2]), "+f"(c[3])
        : "r"(a0), "r"(a1), "r"(a2), "r"(a3), "r"(b0), "r"(b1));
}

__device__ __forceinline__ void grid_barrier_h(unsigned* target) {
    __syncthreads();
    if (threadIdx.x == 0) {
        __threadfence();
        atomicAdd(&g_barg[(blockIdx.x >> 4) * 64], 1u);
    }
    *target += 16;
    if (threadIdx.x < 8) {
        volatile unsigned* c = &g_barg[threadIdx.x * 64];
        while (*c < *target) { }
    }
    __threadfence();
    __syncthreads();
}

__global__ void __launch_bounds__(RTHREADS, 1) gru_recurrent_kernel(
    const float* __restrict__ gk,
    const float* __restrict__ ck,
    float* __restrict__ out)
{
    extern __shared__ unsigned smem[];
    unsigned* WgS = smem + OFF_WG;
    unsigned* WcS = smem + OFF_WC;
    float* Red = (float*)(smem + OFF_RED);

    const int tid  = threadIdx.x;
    const int warp = tid >> 5;
    const int lane = tid & 31;
    const int g    = lane >> 2;       // groupID (0..7)
    const int tg   = lane & 3;        // threadID_in_group

    const int p = blockIdx.x;
    const int jbaseA = p * 16;
    const int jbaseB = p * 8;
    const float* __restrict__ Ug = gk + (size_t)DIN * G2;
    const float* __restrict__ Uc = ck + (size_t)DIN * HID;

    // ---- preload + pack weight slices (once), transposed [j][k] ----
    for (int idx = tid; idx < 1024 * 16; idx += RTHREADS) {
        int k = idx >> 4, j = idx & 15;
        WgS[j * WSTRIDE + k] = packhl(Ug[(size_t)k * G2 + jbaseA + j]);
    }
    for (int idx = tid; idx < 1024 * 8; idx += RTHREADS) {
        int k = idx >> 3, j = idx & 7;
        WcS[j * WSTRIDE + k] = packhl(Uc[(size_t)k * HID + jbaseB + j]);
    }
    __syncthreads();

    unsigned bar_target = 0;
    const int kw = warp * 128;        // this warp's k-range base

    for (int t = 0; t < TS; ++t) {
        // =================== Phase A: gates ===================
        const int o0 = tid, o1 = tid + 256;
        const int bA0 = o0 >> 4, jA0 = o0 & 15;
        const int bA1 = o1 >> 4, jA1 = o1 & 15;
        float xg0 = __ldcg(&g_XG[((size_t)(bA0 * TS + t)) * G2 + jbaseA + jA0]);
        float xg1 = __ldcg(&g_XG[((size_t)(bA1 * TS + t)) * G2 + jbaseA + jA1]);
        unsigned hE0p = 0u, hE1p = 0u;
        if (p < 64) {
            hE0p = __ldcg(&g_h[bA0 * HID + jbaseA + jA0]);
            hE1p = __ldcg(&g_h[bA1 * HID + jbaseA + jA1]);
        }

        float cA[4][4];
#pragma unroll
        for (int i = 0; i < 4; ++i)
#pragma unroll
            for (int j = 0; j < 4; ++j) cA[i][j] = 0.0f;

#pragma unroll
        for (int ki = 0; ki < 16; ++ki) {
            const int kg = kw + ki * 8;
            // A fragments: direct L2 loads (packed u32 pairs)
            uint2 va0 = __ldcg((const uint2*)&g_h[(g)      * HID + kg + 2 * tg]);
            uint2 va1 = __ldcg((const uint2*)&g_h[(g + 8)  * HID + kg + 2 * tg]);
            uint2 va2 = __ldcg((const uint2*)&g_h[(g + 16) * HID + kg + 2 * tg]);
            uint2 va3 = __ldcg((const uint2*)&g_h[(g + 24) * HID + kg + 2 * tg]);
            // W fragments from smem
            uint2 w0 = *(const uint2*)&WgS[(g)     * WSTRIDE + kg + 2 * tg];
            uint2 w1 = *(const uint2*)&WgS[(g + 8) * WSTRIDE + kg + 2 * tg];
            unsigned n0p1b0 = __byte_perm(w0.x, 0, 0x1010);
            unsigned n0p1b1 = __byte_perm(w0.y, 0, 0x1010);
            unsigned n0p2b0 = w0.x >> 16, n0p2b1 = w0.y >> 16;
            unsigned n1p1b0 = __byte_perm(w1.x, 0, 0x1010);
            unsigned n1p1b1 = __byte_perm(w1.y, 0, 0x1010);
            unsigned n1p2b0 = w1.x >> 16, n1p2b1 = w1.y >> 16;
            // m-tile 0
            mma_bf16(cA[0], va0.x, va1.x, va0.y, va1.y, n0p1b0, n0p1b1);
            mma_bf16(cA[0], va0.x, va1.x, va0.y, va1.y, n0p2b0, n0p2b1);
            mma_bf16(cA[1], va0.x, va1.x, va0.y, va1.y, n1p1b0, n1p1b1);
            mma_bf16(cA[1], va0.x, va1.x, va0.y, va1.y, n1p2b0, n1p2b1);
            // m-tile 1
            mma_bf16(cA[2], va2.x, va3.x, va2.y, va3.y, n0p1b0, n0p1b1);
            mma_bf16(cA[2], va2.x, va3.x, va2.y, va3.y, n0p2b0, n0p2b1);
            mma_bf16(cA[3], va2.x, va3.x, va2.y, va3.y, n1p1b0, n1p1b1);
            mma_bf16(cA[3], va2.x, va3.x, va2.y, va3.y, n1p2b0, n1p2b1);
        }
        // per-warp partials
#pragma unroll
        for (int m = 0; m < 2; ++m)
#pragma unroll
            for (int n = 0; n < 2; ++n) {
                float* dst = &Red[warp * 512 + (m * 16 + g) * 16 + n * 8 + 2 * tg];
                *(float2*)dst         = make_float2(cA[m * 2 + n][0], cA[m * 2 + n][1]);
                *(float2*)(dst + 128) = make_float2(cA[m * 2 + n][2], cA[m * 2 + n][3]);
            }
        __syncthreads();
        {
            float s0 = 0.f, s1 = 0.f;
#pragma unroll
            for (int w = 0; w < 8; ++w) { s0 += Red[w * 512 + o0]; s1 += Red[w * 512 + o1]; }
            float sg0 = 1.0f / (1.0f + expf(-(s0 + xg0)));
            float sg1 = 1.0f / (1.0f + expf(-(s1 + xg1)));
            if (p < 64) {
                __stcg(&g_rh[bA0 * HID + jbaseA + jA0], packhl(sg0 * unpackhl(hE0p)));
                __stcg(&g_rh[bA1 * HID + jbaseA + jA1], packhl(sg1 * unpackhl(hE1p)));
            } else {
                __stcg(&g_u[bA0 * HID + (jbaseA - 1024) + jA0], sg0);
                __stcg(&g_u[bA1 * HID + (jbaseA - 1024) + jA1], sg1);
            }
        }
        grid_barrier_h(&bar_target);

        // =================== Phase B: candidate + update ===================
        const int bB = tid >> 3, jB = tid & 7;
        float xc = __ldcg(&g_XC[((size_t)(bB * TS + t)) * HID + jbaseB + jB]);
        float uv = __ldcg(&g_u[bB * HID + jbaseB + jB]);
        unsigned hvp = __ldcg(&g_h[bB * HID + jbaseB + jB]);

        float cB[2][4];
#pragma unroll
        for (int i = 0; i < 2; ++i)
#pragma unroll
            for (int j = 0; j < 4; ++j) cB[i][j] = 0.0f;

#pragma unroll
        for (int ki = 0; ki < 16; ++ki) {
            const int kg = kw + ki * 8;
            uint2 va0 = __ldcg((const uint2*)&g_rh[(g)      * HID + kg + 2 * tg]);
            uint2 va1 = __ldcg((const uint2*)&g_rh[(g + 8)  * HID + kg + 2 * tg]);
            uint2 va2 = __ldcg((const uint2*)&g_rh[(g + 16) * HID + kg + 2 * tg]);
            uint2 va3 = __ldcg((const uint2*)&g_rh[(g + 24) * HID + kg + 2 * tg]);
            uint2 w0 = *(const uint2*)&WcS[(g) * WSTRIDE + kg + 2 * tg];
            unsigned p1b0 = __byte_perm(w0.x, 0, 0x1010);
            unsigned p1b1 = __byte_perm(w0.y, 0, 0x1010);
            unsigned p2b0 = w0.x >> 16, p2b1 = w0.y >> 16;
            mma_bf16(cB[0], va0.x, va1.x, va0.y, va1.y, p1b0, p1b1);
            mma_bf16(cB[0], va0.x, va1.x, va0.y, va1.y, p2b0, p2b1);
            mma_bf16(cB[1], va2.x, va3.x, va2.y, va3.y, p1b0, p1b1);
            mma_bf16(cB[1], va2.x, va3.x, va2.y, va3.y, p2b0, p2b1);
        }
#pragma unroll
        for (int m = 0; m < 2; ++m) {
            float* dst = &Red[warp * 256 + (m * 16 + g) * 8 + 2 * tg];
            *(float2*)dst        = make_float2(cB[m][0], cB[m][1]);
            *(float2*)(dst + 64) = make_float2(cB[m][2], cB[m][3]);
        }
        __syncthreads();
        {
            float s = 0.f;
#pragma unroll
            for (int w = 0; w < 8; ++w) s += Red[w * 256 + tid];
            float cc = tanhf(s + xc);
            float hv = unpackhl(hvp);
            float hn = uv * hv + (1.0f - uv) * cc;
            __stcg(&g_h[bB * HID + jbaseB + jB], packhl(hn));
            out[((size_t)bB * TS + t) * HID + jbaseB + jB] = hn;
        }
        grid_barrier_h(&bar_target);
    }
}

// ---------------- launch ----------------
extern "C" void kernel_launch(void* const* d_in, const int* in_sizes, int n_in,
                              void* d_out, int out_size) {
    const float* X  = (const float*)d_in[0];
    const float* gk = (const float*)d_in[1];
    const float* gb = (const float*)d_in[2];
    const float* ck = (const float*)d_in[3];
    const float* cb = (const float*)d_in[4];
    float* out = (float*)d_out;
    (void)in_sizes; (void)n_in; (void)out_size;

    void* pa = nullptr; void* pb = nullptr;
    cudaGetSymbolAddress(&pa, g_XG);
    cudaGetSymbolAddress(&pb, g_XC);
    float* xg_ptr = (float*)pa;
    float* xc_ptr = (float*)pb;

    cudaFuncSetAttribute(gru_recurrent_kernel,
                         cudaFuncAttributeMaxDynamicSharedMemorySize,
                         SMEM_U32 * (int)sizeof(unsigned));

    gru_init_kernel<<<RBLOCKS, 256>>>();
    {
        dim3 grid(G2 / BN, (NB * TS) / BM);
        sgemm_bias_kernel<<<grid, 256>>>(X, gk, gb, xg_ptr, NB * TS, G2, DIN, G2);
    }
    {
        dim3 grid(HID / BN, (NB * TS) / BM);
        sgemm_bias_kernel<<<grid, 256>>>(X, ck, cb, xc_ptr, NB * TS, HID, DIN, HID);
    }
    gru_recurrent_kernel<<<RBLOCKS, RTHREADS, SMEM_U32 * sizeof(unsigned)>>>(gk, ck, out);
}

// round 13
// speedup vs baseline: 1.2694x; 1.2694x over previous
#include <cuda_runtime.h>
#include <cuda_bf16.h>
#include <math.h>

#define TS   512
#define NB   32
#define DIN  512
#define HID  1024
#define G2   2048

// ---------------- global scratch ----------------
__device__ float    g_XG[(size_t)TS * NB * G2];
__device__ float    g_XC[(size_t)TS * NB * HID];
__device__ unsigned g_h [NB * HID];      // packed bf16 hi|lo<<16
__device__ unsigned g_rh[NB * HID];      // packed
__device__ float    g_u [NB * HID];
__device__ unsigned g_barg[8 * 64];

__global__ void gru_init_kernel() {
    int idx = blockIdx.x * blockDim.x + threadIdx.x;
    if (idx < NB * HID) g_h[idx] = 0u;
    if (idx < 8 * 64) g_barg[idx] = 0u;
}

// ---------------- pack/unpack helpers ----------------
__device__ __forceinline__ unsigned packhl(float v) {
    __nv_bfloat16 hb = __float2bfloat16(v);
    unsigned short hu = *reinterpret_cast<unsigned short*>(&hb);
    float hf = __uint_as_float((unsigned)hu << 16);
    __nv_bfloat16 lb = __float2bfloat16(v - hf);
    unsigned short lu = *reinterpret_cast<unsigned short*>(&lb);
    return (unsigned)hu | ((unsigned)lu << 16);
}
__device__ __forceinline__ float unpackhl(unsigned x) {
    return __uint_as_float(x << 16) + __uint_as_float(x & 0xFFFF0000u);
}

// ---------------- precompute GEMM (unchanged) ----------------
#define BM 128
#define BN 64
#define BK 16
#define APAD 132

__global__ void __launch_bounds__(256) sgemm_bias_kernel(
    const float* __restrict__ A, const float* __restrict__ W,
    const float* __restrict__ bias, float* __restrict__ C,
    int M, int N, int K, int ldw)
{
    __shared__ float As[BK * APAD];
    __shared__ float Ws[BK * BN];

    const int tid = threadIdx.x;
    const int tx = tid & 15;
    const int ty = tid >> 4;
    const int m0 = blockIdx.y * BM;
    const int n0 = blockIdx.x * BN;

    float acc[8][4];
#pragma unroll
    for (int i = 0; i < 8; ++i)
#pragma unroll
        for (int j = 0; j < 4; ++j) acc[i][j] = 0.0f;

    for (int k0 = 0; k0 < K; k0 += BK) {
        {
            const int kq = tid & 3;
            const int mr = tid >> 2;
#pragma unroll
            for (int it = 0; it < 2; ++it) {
                int m = mr + it * 64;
                float4 v = *(const float4*)&A[(size_t)(m0 + m) * K + k0 + kq * 4];
                As[(kq * 4 + 0) * APAD + m] = v.x;
                As[(kq * 4 + 1) * APAD + m] = v.y;
                As[(kq * 4 + 2) * APAD + m] = v.z;
                As[(kq * 4 + 3) * APAD + m] = v.w;
            }
        }
        {
            const int nq = tid & 15;
            const int kr = tid >> 4;
            float4 v = *(const float4*)&W[(size_t)(k0 + kr) * ldw + n0 + nq * 4];
            *(float4*)&Ws[kr * BN + nq * 4] = v;
        }
        __syncthreads();
#pragma unroll
        for (int kk = 0; kk < BK; ++kk) {
            float4 w4 = *(const float4*)&Ws[kk * BN + tx * 4];
            float4 a0 = *(const float4*)&As[kk * APAD + ty * 8];
            float4 a1 = *(const float4*)&As[kk * APAD + ty * 8 + 4];
            float a[8];
            a[0] = a0.x; a[1] = a0.y; a[2] = a0.z; a[3] = a0.w;
            a[4] = a1.x; a[5] = a1.y; a[6] = a1.z; a[7] = a1.w;
#pragma unroll
            for (int i = 0; i < 8; ++i) {
                acc[i][0] += a[i] * w4.x;
                acc[i][1] += a[i] * w4.y;
                acc[i][2] += a[i] * w4.z;
                acc[i][3] += a[i] * w4.w;
            }
        }
        __syncthreads();
    }

    float4 bv = *(const float4*)&bias[n0 + tx * 4];
#pragma unroll
    for (int i = 0; i < 8; ++i) {
        float4 o;
        o.x = acc[i][0] + bv.x;
        o.y = acc[i][1] + bv.y;
        o.z = acc[i][2] + bv.z;
        o.w = acc[i][3] + bv.w;
        *(float4*)&C[(size_t)(m0 + ty * 8 + i) * N + n0 + tx * 4] = o;
    }
}

// ---------------- persistent recurrence (bf16 2-pass mma, per-warp slice staging) ----------------
#define RBLOCKS  128
#define RTHREADS 256
#define SLICE    4096                // u32 per warp slice (32 rows x 128 cols)

// smem layout (u32 offsets)
#define OFF_WG   0                   // [16 j][1024 k] swizzled (col' = (k+8j)&1023)
#define OFF_WC   16384               // [8 j][1024 k]
#define OFF_H    24576               // 8 warps x 4096 (col' = (col+8row)&127)
#define SMEM_U32 57344               // 229376 bytes

__device__ __forceinline__ void mma_bf16(float* c, unsigned a0, unsigned a1,
                                         unsigned a2, unsigned a3,
                                         unsigned b0, unsigned b1) {
    asm("mma.sync.aligned.m16n8k16.row.col.f32.bf16.bf16.f32 "
        "{%0,%1,%2,%3}, {%4,%5,%6,%7}, {%8,%9}, {%0,%1,%2,%3};"
        : "+f"(c[0]), "+f"(c[1]), "+f"(c[2]), "+f"(c[3])
        : "r"(a0), "r"(a1), "r"(a2), "r"(a3), "r"(b0), "r"(b1));
}
__device__ __forceinline__ void cp16(unsigned saddr, const void* g) {
    asm volatile("cp.async.cg.shared.global [%0], [%1], 16;" :: "r"(saddr), "l"(g));
}
#define CP_COMMIT() asm volatile("cp.async.commit_group;")
#define CP_WAIT(n)  asm volatile("cp.async.wait_group %0;" :: "n"(n))

__device__ __forceinline__ void grid_barrier_h(unsigned* target) {
    __syncthreads();
    if (threadIdx.x == 0) {
        __threadfence();
        atomicAdd(&g_barg[(blockIdx.x >> 4) * 64], 1u);
    }
    *target += 16;
    if (threadIdx.x < 8) {
        volatile unsigned* c = &g_barg[threadIdx.x * 64];
        while (*c < *target) { }
    }
    __threadfence();
    __syncthreads();
}

// stage this warp's 32x128 slice of src (packed [b][1024]) in two commit groups
__device__ __forceinline__ void stage_slice(unsigned sbase, const unsigned* __restrict__ src,
                                            int warp, int lane, int kw) {
    const unsigned dst0 = sbase + (unsigned)((OFF_H + warp * SLICE) * 4);
    const int col = lane * 4;
#pragma unroll
    for (int r = 0; r < 16; ++r) {
        int colp = (col + 8 * r) & 127;
        cp16(dst0 + (unsigned)((r * 128 + colp) * 4), src + (size_t)r * HID + kw + col);
    }
    CP_COMMIT();
#pragma unroll
    for (int r = 16; r < 32; ++r) {
        int colp = (col + 8 * r) & 127;
        cp16(dst0 + (unsigned)((r * 128 + colp) * 4), src + (size_t)r * HID + kw + col);
    }
    CP_COMMIT();
}

__global__ void __launch_bounds__(RTHREADS, 1) gru_recurrent_kernel(
    const float* __restrict__ gk,
    const float* __restrict__ ck,
    float* __restrict__ out)
{
    extern __shared__ unsigned smem[];
    const unsigned sbase = (unsigned)__cvta_generic_to_shared(smem);
    unsigned* WgS = smem + OFF_WG;
    unsigned* WcS = smem + OFF_WC;

    const int tid  = threadIdx.x;
    const int warp = tid >> 5;
    const int lane = tid & 31;
    const int g    = lane >> 2;       // groupID (0..7)
    const int tg   = lane & 3;        // threadID_in_group

    const int p = blockIdx.x;
    const int jbaseA = p * 16;
    const int jbaseB = p * 8;
    const float* __restrict__ Ug = gk + (size_t)DIN * G2;
    const float* __restrict__ Uc = ck + (size_t)DIN * HID;

    unsigned* Sw = smem + OFF_H + warp * SLICE;   // this warp's slice
    float* RedW  = (float*)Sw;                    // per-warp Red partial aliases slice

    // ---- preload + pack weight slices (once), swizzled [j][(k+8j)&1023] ----
    for (int idx = tid; idx < 1024 * 16; idx += RTHREADS) {
        int k = idx >> 4, j = idx & 15;
        WgS[j * 1024 + ((k + 8 * j) & 1023)] = packhl(Ug[(size_t)k * G2 + jbaseA + j]);
    }
    for (int idx = tid; idx < 1024 * 8; idx += RTHREADS) {
        int k = idx >> 3, j = idx & 7;
        WcS[j * 1024 + ((k + 8 * j) & 1023)] = packhl(Uc[(size_t)k * HID + jbaseB + j]);
    }
    __syncthreads();

    unsigned bar_target = 0;
    const int kw = warp * 128;        // this warp's k-range base

    for (int t = 0; t < TS; ++t) {
        // =================== Phase A: gates ===================
        stage_slice(sbase, g_h, warp, lane, kw);

        const int o0 = tid, o1 = tid + 256;
        const int bA0 = o0 >> 4, jA0 = o0 & 15;
        const int bA1 = o1 >> 4, jA1 = o1 & 15;
        float xg0 = __ldcg(&g_XG[((size_t)(bA0 * TS + t)) * G2 + jbaseA + jA0]);
        float xg1 = __ldcg(&g_XG[((size_t)(bA1 * TS + t)) * G2 + jbaseA + jA1]);
        unsigned hE0p = 0u, hE1p = 0u;
        if (p < 64) {
            hE0p = __ldcg(&g_h[bA0 * HID + jbaseA + jA0]);
            hE1p = __ldcg(&g_h[bA1 * HID + jbaseA + jA1]);
        }

        float cA[4][4];
#pragma unroll
        for (int i = 0; i < 4; ++i)
#pragma unroll
            for (int j = 0; j < 4; ++j) cA[i][j] = 0.0f;

        // m-tiles 0 (rows g, g+8) after first group arrives
        CP_WAIT(1); __syncwarp();
#pragma unroll
        for (int ki = 0; ki < 16; ++ki) {
            const int kl = ki * 8 + 2 * tg;
            const int kg = kw + ki * 8;
            uint2 va0 = *(const uint2*)&Sw[(g)     * 128 + ((kl + 8 * g) & 127)];
            uint2 va1 = *(const uint2*)&Sw[(g + 8) * 128 + ((kl + 8 * (g + 8)) & 127)];
            uint2 w0 = *(const uint2*)&WgS[(g)     * 1024 + ((kg + 2 * tg + 8 * g) & 1023)];
            uint2 w1 = *(const uint2*)&WgS[(g + 8) * 1024 + ((kg + 2 * tg + 8 * (g + 8)) & 1023)];
            unsigned n0p1b0 = __byte_perm(w0.x, 0, 0x1010);
            unsigned n0p1b1 = __byte_perm(w0.y, 0, 0x1010);
            unsigned n0p2b0 = w0.x >> 16, n0p2b1 = w0.y >> 16;
            unsigned n1p1b0 = __byte_perm(w1.x, 0, 0x1010);
            unsigned n1p1b1 = __byte_perm(w1.y, 0, 0x1010);
            unsigned n1p2b0 = w1.x >> 16, n1p2b1 = w1.y >> 16;
            mma_bf16(cA[0], va0.x, va1.x, va0.y, va1.y, n0p1b0, n0p1b1);
            mma_bf16(cA[0], va0.x, va1.x, va0.y, va1.y, n0p2b0, n0p2b1);
            mma_bf16(cA[1], va0.x, va1.x, va0.y, va1.y, n1p1b0, n1p1b1);
            mma_bf16(cA[1], va0.x, va1.x, va0.y, va1.y, n1p2b0, n1p2b1);
        }
        // m-tiles 1 (rows g+16, g+24) after second group
        CP_WAIT(0); __syncwarp();
#pragma unroll
        for (int ki = 0; ki < 16; ++ki) {
            const int kl = ki * 8 + 2 * tg;
            const int kg = kw + ki * 8;
            uint2 va2 = *(const uint2*)&Sw[(g + 16) * 128 + ((kl + 8 * (g + 16)) & 127)];
            uint2 va3 = *(const uint2*)&Sw[(g + 24) * 128 + ((kl + 8 * (g + 24)) & 127)];
            uint2 w0 = *(const uint2*)&WgS[(g)     * 1024 + ((kg + 2 * tg + 8 * g) & 1023)];
            uint2 w1 = *(const uint2*)&WgS[(g + 8) * 1024 + ((kg + 2 * tg + 8 * (g + 8)) & 1023)];
            unsigned n0p1b0 = __byte_perm(w0.x, 0, 0x1010);
            unsigned n0p1b1 = __byte_perm(w0.y, 0, 0x1010);
            unsigned n0p2b0 = w0.x >> 16, n0p2b1 = w0.y >> 16;
            unsigned n1p1b0 = __byte_perm(w1.x, 0, 0x1010);
            unsigned n1p1b1 = __byte_perm(w1.y, 0, 0x1010);
            unsigned n1p2b0 = w1.x >> 16, n1p2b1 = w1.y >> 16;
            mma_bf16(cA[2], va2.x, va3.x, va2.y, va3.y, n0p1b0, n0p1b1);
            mma_bf16(cA[2], va2.x, va3.x, va2.y, va3.y, n0p2b0, n0p2b1);
            mma_bf16(cA[3], va2.x, va3.x, va2.y, va3.y, n1p1b0, n1p1b1);
            mma_bf16(cA[3], va2.x, va3.x, va2.y, va3.y, n1p2b0, n1p2b1);
        }
        // per-warp partials into own slice (reads of slice are complete)
        __syncwarp();
#pragma unroll
        for (int m = 0; m < 2; ++m)
#pragma unroll
            for (int n = 0; n < 2; ++n) {
                float* dst = &RedW[(m * 16 + g) * 16 + n * 8 + 2 * tg];
                *(float2*)dst         = make_float2(cA[m * 2 + n][0], cA[m * 2 + n][1]);
                *(float2*)(dst + 128) = make_float2(cA[m * 2 + n][2], cA[m * 2 + n][3]);
            }
        __syncthreads();
        {
            float s0 = 0.f, s1 = 0.f;
#pragma unroll
            for (int w = 0; w < 8; ++w) {
                const float* Rw = (const float*)(smem + OFF_H + w * SLICE);
                s0 += Rw[o0]; s1 += Rw[o1];
            }
            float sg0 = 1.0f / (1.0f + expf(-(s0 + xg0)));
            float sg1 = 1.0f / (1.0f + expf(-(s1 + xg1)));
            if (p < 64) {
                __stcg(&g_rh[bA0 * HID + jbaseA + jA0], packhl(sg0 * unpackhl(hE0p)));
                __stcg(&g_rh[bA1 * HID + jbaseA + jA1], packhl(sg1 * unpackhl(hE1p)));
            } else {
                __stcg(&g_u[bA0 * HID + (jbaseA - 1024) + jA0], sg0);
                __stcg(&g_u[bA1 * HID + (jbaseA - 1024) + jA1], sg1);
            }
        }
        grid_barrier_h(&bar_target);

        // =================== Phase B: candidate + update ===================
        stage_slice(sbase, g_rh, warp, lane, kw);

        const int bB = tid >> 3, jB = tid & 7;
        float xc = __ldcg(&g_XC[((size_t)(bB * TS + t)) * HID + jbaseB + jB]);
        float uv = __ldcg(&g_u[bB * HID + jbaseB + jB]);
        unsigned hvp = __ldcg(&g_h[bB * HID + jbaseB + jB]);

        float cB[2][4];
#pragma unroll
        for (int i = 0; i < 2; ++i)
#pragma unroll
            for (int j = 0; j < 4; ++j) cB[i][j] = 0.0f;

        CP_WAIT(1); __syncwarp();
#pragma unroll
        for (int ki = 0; ki < 16; ++ki) {
            const int kl = ki * 8 + 2 * tg;
            const int kg = kw + ki * 8;
            uint2 va0 = *(const uint2*)&Sw[(g)     * 128 + ((kl + 8 * g) & 127)];
            uint2 va1 = *(const uint2*)&Sw[(g + 8) * 128 + ((kl + 8 * (g + 8)) & 127)];
            uint2 w0 = *(const uint2*)&WcS[(g) * 1024 + ((kg + 2 * tg + 8 * g) & 1023)];
            unsigned p1b0 = __byte_perm(w0.x, 0, 0x1010);
            unsigned p1b1 = __byte_perm(w0.y, 0, 0x1010);
            unsigned p2b0 = w0.x >> 16, p2b1 = w0.y >> 16;
            mma_bf16(cB[0], va0.x, va1.x, va0.y, va1.y, p1b0, p1b1);
            mma_bf16(cB[0], va0.x, va1.x, va0.y, va1.y, p2b0, p2b1);
        }
        CP_WAIT(0); __syncwarp();
#pragma unroll
        for (int ki = 0; ki < 16; ++ki) {
            const int kl = ki * 8 + 2 * tg;
            const int kg = kw + ki * 8;
            uint2 va2 = *(const uint2*)&Sw[(g + 16) * 128 + ((kl + 8 * (g + 16)) & 127)];
            uint2 va3 = *(const uint2*)&Sw[(g + 24) * 128 + ((kl + 8 * (g + 24)) & 127)];
            uint2 w0 = *(const uint2*)&WcS[(g) * 1024 + ((kg + 2 * tg + 8 * g) & 1023)];
            unsigned p1b0 = __byte_perm(w0.x, 0, 0x1010);
            unsigned p1b1 = __byte_perm(w0.y, 0, 0x1010);
            unsigned p2b0 = w0.x >> 16, p2b1 = w0.y >> 16;
            mma_bf16(cB[1], va2.x, va3.x, va2.y, va3.y, p1b0, p1b1);
            mma_bf16(cB[1], va2.x, va3.x, va2.y, va3.y, p2b0, p2b1);
        }
        __syncwarp();
#pragma unroll
        for (int m = 0; m < 2; ++m) {
            float* dst = &RedW[(m * 16 + g) * 8 + 2 * tg];
            *(float2*)dst        = make_float2(cB[m][0], cB[m][1]);
            *(float2*)(dst + 64) = make_float2(cB[m][2], cB[m][3]);
        }
        __syncthreads();
        {
            float s = 0.f;
#pragma unroll
            for (int w = 0; w < 8; ++w)
                s += ((const float*)(smem + OFF_H + w * SLICE))[tid];
            float cc = tanhf(s + xc);
            float hv = unpackhl(hvp);
            float hn = uv * hv + (1.0f - uv) * cc;
            __stcg(&g_h[bB * HID + jbaseB + jB], packhl(hn));
            out[((size_t)bB * TS + t) * HID + jbaseB + jB] = hn;
        }
        grid_barrier_h(&bar_target);
    }
}

// ---------------- launch ----------------
extern "C" void kernel_launch(void* const* d_in, const int* in_sizes, int n_in,
                              void* d_out, int out_size) {
    const float* X  = (const float*)d_in[0];
    const float* gk = (const float*)d_in[1];
    const float* gb = (const float*)d_in[2];
    const float* ck = (const float*)d_in[3];
    const float* cb = (const float*)d_in[4];
    float* out = (float*)d_out;
    (void)in_sizes; (void)n_in; (void)out_size;

    void* pa = nullptr; void* pb = nullptr;
    cudaGetSymbolAddress(&pa, g_XG);
    cudaGetSymbolAddress(&pb, g_XC);
    float* xg_ptr = (float*)pa;
    float* xc_ptr = (float*)pb;

    cudaFuncSetAttribute(gru_recurrent_kernel,
                         cudaFuncAttributeMaxDynamicSharedMemorySize,
                         SMEM_U32 * (int)sizeof(unsigned));

    gru_init_kernel<<<RBLOCKS, 256>>>();
    {
        dim3 grid(G2 / BN, (NB * TS) / BM);
        sgemm_bias_kernel<<<grid, 256>>>(X, gk, gb, xg_ptr, NB * TS, G2, DIN, G2);
    }
    {
        dim3 grid(HID / BN, (NB * TS) / BM);
        sgemm_bias_kernel<<<grid, 256>>>(X, ck, cb, xc_ptr, NB * TS, HID, DIN, HID);
    }
    gru_recurrent_kernel<<<RBLOCKS, RTHREADS, SMEM_U32 * sizeof(unsigned)>>>(gk, ck, out);
}

// round 14
// speedup vs baseline: 1.3159x; 1.0366x over previous
#include <cuda_runtime.h>
#include <cuda_bf16.h>
#include <math.h>

#define TS   512
#define NB   32
#define DIN  512
#define HID  1024
#define G2   2048

// ---------------- global scratch ----------------
__device__ float    g_XG[(size_t)TS * NB * G2];
__device__ float    g_XC[(size_t)TS * NB * HID];
__device__ unsigned g_h [NB * HID];      // packed bf16 hi|lo<<16
__device__ unsigned g_rh[NB * HID];      // packed
__device__ float    g_u [NB * HID];
__device__ unsigned g_barg[8 * 64];

__global__ void gru_init_kernel() {
    int idx = blockIdx.x * blockDim.x + threadIdx.x;
    if (idx < NB * HID) g_h[idx] = 0u;
    if (idx < 8 * 64) g_barg[idx] = 0u;
}

// ---------------- pack/unpack helpers ----------------
__device__ __forceinline__ unsigned packhl(float v) {
    __nv_bfloat16 hb = __float2bfloat16(v);
    unsigned short hu = *reinterpret_cast<unsigned short*>(&hb);
    float hf = __uint_as_float((unsigned)hu << 16);
    __nv_bfloat16 lb = __float2bfloat16(v - hf);
    unsigned short lu = *reinterpret_cast<unsigned short*>(&lb);
    return (unsigned)hu | ((unsigned)lu << 16);
}
__device__ __forceinline__ float unpackhl(unsigned x) {
    return __uint_as_float(x << 16) + __uint_as_float(x & 0xFFFF0000u);
}

// ---------------- precompute GEMM (unchanged) ----------------
#define BM 128
#define BN 64
#define BK 16
#define APAD 132

__global__ void __launch_bounds__(256) sgemm_bias_kernel(
    const float* __restrict__ A, const float* __restrict__ W,
    const float* __restrict__ bias, float* __restrict__ C,
    int M, int N, int K, int ldw)
{
    __shared__ float As[BK * APAD];
    __shared__ float Ws[BK * BN];

    const int tid = threadIdx.x;
    const int tx = tid & 15;
    const int ty = tid >> 4;
    const int m0 = blockIdx.y * BM;
    const int n0 = blockIdx.x * BN;

    float acc[8][4];
#pragma unroll
    for (int i = 0; i < 8; ++i)
#pragma unroll
        for (int j = 0; j < 4; ++j) acc[i][j] = 0.0f;

    for (int k0 = 0; k0 < K; k0 += BK) {
        {
            const int kq = tid & 3;
            const int mr = tid >> 2;
#pragma unroll
            for (int it = 0; it < 2; ++it) {
                int m = mr + it * 64;
                float4 v = *(const float4*)&A[(size_t)(m0 + m) * K + k0 + kq * 4];
                As[(kq * 4 + 0) * APAD + m] = v.x;
                As[(kq * 4 + 1) * APAD + m] = v.y;
                As[(kq * 4 + 2) * APAD + m] = v.z;
                As[(kq * 4 + 3) * APAD + m] = v.w;
            }
        }
        {
            const int nq = tid & 15;
            const int kr = tid >> 4;
            float4 v = *(const float4*)&W[(size_t)(k0 + kr) * ldw + n0 + nq * 4];
            *(float4*)&Ws[kr * BN + nq * 4] = v;
        }
        __syncthreads();
#pragma unroll
        for (int kk = 0; kk < BK; ++kk) {
            float4 w4 = *(const float4*)&Ws[kk * BN + tx * 4];
            float4 a0 = *(const float4*)&As[kk * APAD + ty * 8];
            float4 a1 = *(const float4*)&As[kk * APAD + ty * 8 + 4];
            float a[8];
            a[0] = a0.x; a[1] = a0.y; a[2] = a0.z; a[3] = a0.w;
            a[4] = a1.x; a[5] = a1.y; a[6] = a1.z; a[7] = a1.w;
#pragma unroll
            for (int i = 0; i < 8; ++i) {
                acc[i][0] += a[i] * w4.x;
                acc[i][1] += a[i] * w4.y;
                acc[i][2] += a[i] * w4.z;
                acc[i][3] += a[i] * w4.w;
            }
        }
        __syncthreads();
    }

    float4 bv = *(const float4*)&bias[n0 + tx * 4];
#pragma unroll
    for (int i = 0; i < 8; ++i) {
        float4 o;
        o.x = acc[i][0] + bv.x;
        o.y = acc[i][1] + bv.y;
        o.z = acc[i][2] + bv.z;
        o.w = acc[i][3] + bv.w;
        *(float4*)&C[(size_t)(m0 + ty * 8 + i) * N + n0 + tx * 4] = o;
    }
}

// ---------------- persistent recurrence (bf16 2-pass mma, one-shot per-warp staging) ----------------
#define RBLOCKS  128
#define RTHREADS 256
#define HSTRIDE  1032                // u32 stride per batch row (1024+8; %32==8)

// smem layout (u32 offsets)
#define OFF_H    0                   // [32][1032] shared h tile; Red aliases this
#define OFF_WG   33024               // [16 j][1032 k] packed
#define OFF_WC   49536               // [8 j][1032 k]
#define SMEM_U32 57792               // 231168 bytes

__device__ __forceinline__ void mma_bf16(float* c, unsigned a0, unsigned a1,
                                         unsigned a2, unsigned a3,
                                         unsigned b0, unsigned b1) {
    asm("mma.sync.aligned.m16n8k16.row.col.f32.bf16.bf16.f32 "
        "{%0,%1,%2,%3}, {%4,%5,%6,%7}, {%8,%9}, {%0,%1,%2,%3};"
        : "+f"(c[0]), "+f"(c[1]), "+f"(c[2]), "+f"(c[3])
        : "r"(a0), "r"(a1), "r"(a2), "r"(a3), "r"(b0), "r"(b1));
}
__device__ __forceinline__ void cp16(unsigned saddr, const void* g) {
    asm volatile("cp.async.cg.shared.global [%0], [%1], 16;" :: "r"(saddr), "l"(g));
}
#define CP_COMMIT() asm volatile("cp.async.commit_group;")
#define CP_WAIT(n)  asm volatile("cp.async.wait_group %0;" :: "n"(n))

__device__ __forceinline__ void grid_barrier_h(unsigned* target) {
    __syncthreads();
    if (threadIdx.x == 0) {
        __threadfence();
        atomicAdd(&g_barg[(blockIdx.x >> 4) * 64], 1u);
    }
    *target += 16;
    if (threadIdx.x < 8) {
        volatile unsigned* c = &g_barg[threadIdx.x * 64];
        while (*c < *target) { }
    }
    __threadfence();
    __syncthreads();
}

// warp w stages its own 32 rows x 128 cols (at col base kw) in ONE commit group
__device__ __forceinline__ void stage_slice(unsigned sbase, const unsigned* __restrict__ src,
                                            int kw, int lane) {
    const int col = kw + lane * 4;
    const unsigned dst = sbase + (unsigned)((OFF_H + col) * 4);
#pragma unroll
    for (int r = 0; r < 32; ++r)
        cp16(dst + (unsigned)(r * HSTRIDE * 4), src + (size_t)r * HID + col);
    CP_COMMIT();
}

__global__ void __launch_bounds__(RTHREADS, 1) gru_recurrent_kernel(
    const float* __restrict__ gk,
    const float* __restrict__ ck,
    float* __restrict__ out)
{
    extern __shared__ unsigned smem[];
    const unsigned sbase = (unsigned)__cvta_generic_to_shared(smem);
    unsigned* Sh  = smem + OFF_H;
    unsigned* WgS = smem + OFF_WG;
    unsigned* WcS = smem + OFF_WC;
    float* Red = (float*)(smem + OFF_H);   // aliases h tile (guarded by syncthreads)

    const int tid  = threadIdx.x;
    const int warp = tid >> 5;
    const int lane = tid & 31;
    const int g    = lane >> 2;       // groupID (0..7)
    const int tg   = lane & 3;        // threadID_in_group

    const int p = blockIdx.x;
    const int jbaseA = p * 16;
    const int jbaseB = p * 8;
    const float* __restrict__ Ug = gk + (size_t)DIN * G2;
    const float* __restrict__ Uc = ck + (size_t)DIN * HID;

    // ---- preload + pack weight slices (once), transposed [j][k] ----
    for (int idx = tid; idx < 1024 * 16; idx += RTHREADS) {
        int k = idx >> 4, j = idx & 15;
        WgS[j * HSTRIDE + k] = packhl(Ug[(size_t)k * G2 + jbaseA + j]);
    }
    for (int idx = tid; idx < 1024 * 8; idx += RTHREADS) {
        int k = idx >> 3, j = idx & 7;
        WcS[j * HSTRIDE + k] = packhl(Uc[(size_t)k * HID + jbaseB + j]);
    }
    __syncthreads();

    unsigned bar_target = 0;
    const int kw = warp * 128;        // this warp's k-range base

    for (int t = 0; t < TS; ++t) {
        // =================== Phase A: gates ===================
        stage_slice(sbase, g_h, kw, lane);

        // prefetch epilogue operands (A now, B's stable ones too)
        const int o0 = tid, o1 = tid + 256;
        const int bA0 = o0 >> 4, jA0 = o0 & 15;
        const int bA1 = o1 >> 4, jA1 = o1 & 15;
        float xg0 = __ldcg(&g_XG[((size_t)(bA0 * TS + t)) * G2 + jbaseA + jA0]);
        float xg1 = __ldcg(&g_XG[((size_t)(bA1 * TS + t)) * G2 + jbaseA + jA1]);
        unsigned hE0p = 0u, hE1p = 0u;
        if (p < 64) {
            hE0p = __ldcg(&g_h[bA0 * HID + jbaseA + jA0]);
            hE1p = __ldcg(&g_h[bA1 * HID + jbaseA + jA1]);
        }
        const int bB = tid >> 3, jB = tid & 7;
        float xc = __ldcg(&g_XC[((size_t)(bB * TS + t)) * HID + jbaseB + jB]);
        unsigned hvp = __ldcg(&g_h[bB * HID + jbaseB + jB]);

        float cA[4][4];
#pragma unroll
        for (int i = 0; i < 4; ++i)
#pragma unroll
            for (int j = 0; j < 4; ++j) cA[i][j] = 0.0f;

        CP_WAIT(0); __syncwarp();
#pragma unroll
        for (int ki = 0; ki < 16; ++ki) {
            const int kg = kw + ki * 8 + 2 * tg;
            uint2 va0 = *(const uint2*)&Sh[(g)      * HSTRIDE + kg];
            uint2 va1 = *(const uint2*)&Sh[(g + 8)  * HSTRIDE + kg];
            uint2 va2 = *(const uint2*)&Sh[(g + 16) * HSTRIDE + kg];
            uint2 va3 = *(const uint2*)&Sh[(g + 24) * HSTRIDE + kg];
            uint2 w0 = *(const uint2*)&WgS[(g)     * HSTRIDE + kg];
            uint2 w1 = *(const uint2*)&WgS[(g + 8) * HSTRIDE + kg];
            unsigned n0p1b0 = __byte_perm(w0.x, 0, 0x1010);
            unsigned n0p1b1 = __byte_perm(w0.y, 0, 0x1010);
            unsigned n0p2b0 = w0.x >> 16, n0p2b1 = w0.y >> 16;
            unsigned n1p1b0 = __byte_perm(w1.x, 0, 0x1010);
            unsigned n1p1b1 = __byte_perm(w1.y, 0, 0x1010);
            unsigned n1p2b0 = w1.x >> 16, n1p2b1 = w1.y >> 16;
            mma_bf16(cA[0], va0.x, va1.x, va0.y, va1.y, n0p1b0, n0p1b1);
            mma_bf16(cA[0], va0.x, va1.x, va0.y, va1.y, n0p2b0, n0p2b1);
            mma_bf16(cA[1], va0.x, va1.x, va0.y, va1.y, n1p1b0, n1p1b1);
            mma_bf16(cA[1], va0.x, va1.x, va0.y, va1.y, n1p2b0, n1p2b1);
            mma_bf16(cA[2], va2.x, va3.x, va2.y, va3.y, n0p1b0, n0p1b1);
            mma_bf16(cA[2], va2.x, va3.x, va2.y, va3.y, n0p2b0, n0p2b1);
            mma_bf16(cA[3], va2.x, va3.x, va2.y, va3.y, n1p1b0, n1p1b1);
            mma_bf16(cA[3], va2.x, va3.x, va2.y, va3.y, n1p2b0, n1p2b1);
        }
        __syncthreads();   // all warps done reading h tile -> Red may alias it
#pragma unroll
        for (int m = 0; m < 2; ++m)
#pragma unroll
            for (int n = 0; n < 2; ++n) {
                float* dst = &Red[warp * 512 + (m * 16 + g) * 16 + n * 8 + 2 * tg];
                *(float2*)dst         = make_float2(cA[m * 2 + n][0], cA[m * 2 + n][1]);
                *(float2*)(dst + 128) = make_float2(cA[m * 2 + n][2], cA[m * 2 + n][3]);
            }
        __syncthreads();
        {
            float s0 = 0.f, s1 = 0.f;
#pragma unroll
            for (int w = 0; w < 8; ++w) { s0 += Red[w * 512 + o0]; s1 += Red[w * 512 + o1]; }
            float sg0 = 1.0f / (1.0f + expf(-(s0 + xg0)));
            float sg1 = 1.0f / (1.0f + expf(-(s1 + xg1)));
            if (p < 64) {
                __stcg(&g_rh[bA0 * HID + jbaseA + jA0], packhl(sg0 * unpackhl(hE0p)));
                __stcg(&g_rh[bA1 * HID + jbaseA + jA1], packhl(sg1 * unpackhl(hE1p)));
            } else {
                __stcg(&g_u[bA0 * HID + (jbaseA - 1024) + jA0], sg0);
                __stcg(&g_u[bA1 * HID + (jbaseA - 1024) + jA1], sg1);
            }
        }
        grid_barrier_h(&bar_target);

        // =================== Phase B: candidate + update ===================
        stage_slice(sbase, g_rh, kw, lane);
        float uv = __ldcg(&g_u[bB * HID + jbaseB + jB]);

        float cB[2][4];
#pragma unroll
        for (int i = 0; i < 2; ++i)
#pragma unroll
            for (int j = 0; j < 4; ++j) cB[i][j] = 0.0f;

        CP_WAIT(0); __syncwarp();
#pragma unroll
        for (int ki = 0; ki < 16; ++ki) {
            const int kg = kw + ki * 8 + 2 * tg;
            uint2 va0 = *(const uint2*)&Sh[(g)      * HSTRIDE + kg];
            uint2 va1 = *(const uint2*)&Sh[(g + 8)  * HSTRIDE + kg];
            uint2 va2 = *(const uint2*)&Sh[(g + 16) * HSTRIDE + kg];
            uint2 va3 = *(const uint2*)&Sh[(g + 24) * HSTRIDE + kg];
            uint2 w0 = *(const uint2*)&WcS[(g) * HSTRIDE + kg];
            unsigned p1b0 = __byte_perm(w0.x, 0, 0x1010);
            unsigned p1b1 = __byte_perm(w0.y, 0, 0x1010);
            unsigned p2b0 = w0.x >> 16, p2b1 = w0.y >> 16;
            mma_bf16(cB[0], va0.x, va1.x, va0.y, va1.y, p1b0, p1b1);
            mma_bf16(cB[0], va0.x, va1.x, va0.y, va1.y, p2b0, p2b1);
            mma_bf16(cB[1], va2.x, va3.x, va2.y, va3.y, p1b0, p1b1);
            mma_bf16(cB[1], va2.x, va3.x, va2.y, va3.y, p2b0, p2b1);
        }
        __syncthreads();
#pragma unroll
        for (int m = 0; m < 2; ++m) {
            float* dst = &Red[warp * 256 + (m * 16 + g) * 8 + 2 * tg];
            *(float2*)dst        = make_float2(cB[m][0], cB[m][1]);
            *(float2*)(dst + 64) = make_float2(cB[m][2], cB[m][3]);
        }
        __syncthreads();
        {
            float s = 0.f;
#pragma unroll
            for (int w = 0; w < 8; ++w) s += Red[w * 256 + tid];
            float cc = tanhf(s + xc);
            float hv = unpackhl(hvp);
            float hn = uv * hv + (1.0f - uv) * cc;
            __stcg(&g_h[bB * HID + jbaseB + jB], packhl(hn));
            out[((size_t)bB * TS + t) * HID + jbaseB + jB] = hn;
        }
        grid_barrier_h(&bar_target);
    }
}

// ---------------- launch ----------------
extern "C" void kernel_launch(void* const* d_in, const int* in_sizes, int n_in,
                              void* d_out, int out_size) {
    const float* X  = (const float*)d_in[0];
    const float* gk = (const float*)d_in[1];
    const float* gb = (const float*)d_in[2];
    const float* ck = (const float*)d_in[3];
    const float* cb = (const float*)d_in[4];
    float* out = (float*)d_out;
    (void)in_sizes; (void)n_in; (void)out_size;

    void* pa = nullptr; void* pb = nullptr;
    cudaGetSymbolAddress(&pa, g_XG);
    cudaGetSymbolAddress(&pb, g_XC);
    float* xg_ptr = (float*)pa;
    float* xc_ptr = (float*)pb;

    cudaFuncSetAttribute(gru_recurrent_kernel,
                         cudaFuncAttributeMaxDynamicSharedMemorySize,
                         SMEM_U32 * (int)sizeof(unsigned));

    gru_init_kernel<<<RBLOCKS, 256>>>();
    {
        dim3 grid(G2 / BN, (NB * TS) / BM);
        sgemm_bias_kernel<<<grid, 256>>>(X, gk, gb, xg_ptr, NB * TS, G2, DIN, G2);
    }
    {
        dim3 grid(HID / BN, (NB * TS) / BM);
        sgemm_bias_kernel<<<grid, 256>>>(X, ck, cb, xc_ptr, NB * TS, HID, DIN, HID);
    }
    gru_recurrent_kernel<<<RBLOCKS, RTHREADS, SMEM_U32 * sizeof(unsigned)>>>(gk, ck, out);
}

// round 17
// speedup vs baseline: 1.4900x; 1.1324x over previous
#include <cuda_runtime.h>
#include <cuda_bf16.h>
#include <math.h>

#define TS   512
#define NB   32
#define DIN  512
#define HID  1024
#define G2   2048

// ---------------- global scratch ----------------
__device__ float    g_XG[(size_t)TS * NB * G2];
__device__ float    g_XC[(size_t)TS * NB * HID];
__device__ unsigned g_h [NB * HID];      // packed bf16 hi|lo<<16
__device__ unsigned g_rh[NB * HID];      // packed
__device__ float    g_u [NB * HID];
__device__ unsigned g_barg[8 * 64];

__global__ void gru_init_kernel() {
    int idx = blockIdx.x * blockDim.x + threadIdx.x;
    if (idx < NB * HID) g_h[idx] = 0u;
    if (idx < 8 * 64) g_barg[idx] = 0u;
}

// ---------------- pack/unpack helpers ----------------
__device__ __forceinline__ unsigned packhl(float v) {
    __nv_bfloat16 hb = __float2bfloat16(v);
    unsigned short hu = *reinterpret_cast<unsigned short*>(&hb);
    float hf = __uint_as_float((unsigned)hu << 16);
    __nv_bfloat16 lb = __float2bfloat16(v - hf);
    unsigned short lu = *reinterpret_cast<unsigned short*>(&lb);
    return (unsigned)hu | ((unsigned)lu << 16);
}
__device__ __forceinline__ float unpackhl(unsigned x) {
    return __uint_as_float(x << 16) + __uint_as_float(x & 0xFFFF0000u);
}

// ---------------- precompute GEMM (unchanged) ----------------
#define BM 128
#define BN 64
#define BK 16
#define APAD 132

__global__ void __launch_bounds__(256) sgemm_bias_kernel(
    const float* __restrict__ A, const float* __restrict__ W,
    const float* __restrict__ bias, float* __restrict__ C,
    int M, int N, int K, int ldw)
{
    __shared__ float As[BK * APAD];
    __shared__ float Ws[BK * BN];

    const int tid = threadIdx.x;
    const int tx = tid & 15;
    const int ty = tid >> 4;
    const int m0 = blockIdx.y * BM;
    const int n0 = blockIdx.x * BN;

    float acc[8][4];
#pragma unroll
    for (int i = 0; i < 8; ++i)
#pragma unroll
        for (int j = 0; j < 4; ++j) acc[i][j] = 0.0f;

    for (int k0 = 0; k0 < K; k0 += BK) {
        {
            const int kq = tid & 3;
            const int mr = tid >> 2;
#pragma unroll
            for (int it = 0; it < 2; ++it) {
                int m = mr + it * 64;
                float4 v = *(const float4*)&A[(size_t)(m0 + m) * K + k0 + kq * 4];
                As[(kq * 4 + 0) * APAD + m] = v.x;
                As[(kq * 4 + 1) * APAD + m] = v.y;
                As[(kq * 4 + 2) * APAD + m] = v.z;
                As[(kq * 4 + 3) * APAD + m] = v.w;
            }
        }
        {
            const int nq = tid & 15;
            const int kr = tid >> 4;
            float4 v = *(const float4*)&W[(size_t)(k0 + kr) * ldw + n0 + nq * 4];
            *(float4*)&Ws[kr * BN + nq * 4] = v;
        }
        __syncthreads();
#pragma unroll
        for (int kk = 0; kk < BK; ++kk) {
            float4 w4 = *(const float4*)&Ws[kk * BN + tx * 4];
            float4 a0 = *(const float4*)&As[kk * APAD + ty * 8];
            float4 a1 = *(const float4*)&As[kk * APAD + ty * 8 + 4];
            float a[8];
            a[0] = a0.x; a[1] = a0.y; a[2] = a0.z; a[3] = a0.w;
            a[4] = a1.x; a[5] = a1.y; a[6] = a1.z; a[7] = a1.w;
#pragma unroll
            for (int i = 0; i < 8; ++i) {
                acc[i][0] += a[i] * w4.x;
                acc[i][1] += a[i] * w4.y;
                acc[i][2] += a[i] * w4.z;
                acc[i][3] += a[i] * w4.w;
            }
        }
        __syncthreads();
    }

    float4 bv = *(const float4*)&bias[n0 + tx * 4];
#pragma unroll
    for (int i = 0; i < 8; ++i) {
        float4 o;
        o.x = acc[i][0] + bv.x;
        o.y = acc[i][1] + bv.y;
        o.z = acc[i][2] + bv.z;
        o.w = acc[i][3] + bv.w;
        *(float4*)&C[(size_t)(m0 + ty * 8 + i) * N + n0 + tx * 4] = o;
    }
}

// ---------------- persistent recurrence (bf16 2-pass mma, batch-split) ----------------
#define RBLOCKS  128
#define RTHREADS 256
#define CK       256                 // k cols per staged chunk
#define HSTR     264                 // u32 stride per batch row in tile (256+8; %32==8)
#define HCBUF    (16 * HSTR)         // 4224 u32 per buffer (16 batch rows)
#define WSTRIDE  1032                // u32 stride per weight j-row

// smem layout (u32 offsets)
#define OFF_HC   0                   // 2 x 4224 h tile; Red (16KB) aliases this
#define OFF_WG   8448                // [32 j][1032 k] packed
#define OFF_WC   41472               // [16 j][1032 k]
#define SMEM_U32 57984               // 231936 bytes

__device__ __forceinline__ void mma_bf16(float* c, unsigned a0, unsigned a1,
                                         unsigned a2, unsigned a3,
                                         unsigned b0, unsigned b1) {
    asm("mma.sync.aligned.m16n8k16.row.col.f32.bf16.bf16.f32 "
        "{%0,%1,%2,%3}, {%4,%5,%6,%7}, {%8,%9}, {%0,%1,%2,%3};"
        : "+f"(c[0]), "+f"(c[1]), "+f"(c[2]), "+f"(c[3])
        : "r"(a0), "r"(a1), "r"(a2), "r"(a3), "r"(b0), "r"(b1));
}
__device__ __forceinline__ void cp16(unsigned saddr, const void* g) {
    asm volatile("cp.async.cg.shared.global [%0], [%1], 16;" :: "r"(saddr), "l"(g));
}
#define CP_COMMIT() asm volatile("cp.async.commit_group;")
#define CP_WAIT(n)  asm volatile("cp.async.wait_group %0;" :: "n"(n))

__device__ __forceinline__ void grid_barrier_h(unsigned* target) {
    __syncthreads();
    if (threadIdx.x == 0) {
        __threadfence();
        atomicAdd(&g_barg[(blockIdx.x >> 4) * 64], 1u);
    }
    *target += 16;
    if (threadIdx.x < 8) {
        volatile unsigned* c = &g_barg[threadIdx.x * 64];
        while (*c < *target) { }
    }
    __threadfence();
    __syncthreads();
}

// stage chunk c: this block's 16 batch rows x CK cols of src (packed [b][1024])
__device__ __forceinline__ void issue_chunk(unsigned sbase, const unsigned* __restrict__ src,
                                            int brow0, int c, int buf) {
    const int tid = threadIdx.x;
#pragma unroll
    for (int it = 0; it < 4; ++it) {
        int u = tid + it * 256;          // 0..1023
        int r = u >> 6, q4 = u & 63;
        const unsigned* gp = src + (size_t)(brow0 + r) * HID + c * CK + q4 * 4;
        unsigned sa = sbase + (unsigned)((OFF_HC + buf * HCBUF + r * HSTR + q4 * 4) * 4);
        cp16(sa, gp);
    }
}

__global__ void __launch_bounds__(RTHREADS, 1) gru_recurrent_kernel(
    const float* __restrict__ gk,
    const float* __restrict__ ck,
    float* __restrict__ out)
{
    extern __shared__ unsigned smem[];
    const unsigned sbase = (unsigned)__cvta_generic_to_shared(smem);
    unsigned* WgS = smem + OFF_WG;
    unsigned* WcS = smem + OFF_WC;
    float* Red = (float*)(smem + OFF_HC);   // aliases h tiles (guarded by syncthreads)

    const int tid  = threadIdx.x;
    const int warp = tid >> 5;
    const int lane = tid & 31;
    const int g    = lane >> 2;       // groupID (0..7)
    const int tg   = lane & 3;        // threadID_in_group

    const int p = blockIdx.x;
    const int q = p >> 1;             // j-slice (0..63)
    const int bhalf = p & 1;          // batch half
    const int brow0 = bhalf * 16;
    const int jbaseA = q * 32;        // 32 gate cols
    const int jbaseB = q * 16;        // 16 cand cols
    const float* __restrict__ Ug = gk + (size_t)DIN * G2;
    const float* __restrict__ Uc = ck + (size_t)DIN * HID;

    // ---- preload + pack weight slices (once), transposed [j][k] ----
    for (int idx = tid; idx < 1024 * 32; idx += RTHREADS) {
        int k = idx >> 5, j = idx & 31;
        WgS[j * WSTRIDE + k] = packhl(Ug[(size_t)k * G2 + jbaseA + j]);
    }
    for (int idx = tid; idx < 1024 * 16; idx += RTHREADS) {
        int k = idx >> 4, j = idx & 15;
        WcS[j * WSTRIDE + k] = packhl(Uc[(size_t)k * HID + jbaseB + j]);
    }
    __syncthreads();

    unsigned bar_target = 0;

    for (int t = 0; t < TS; ++t) {
        // =================== Phase A: gates ===================
        issue_chunk(sbase, g_h, brow0, 0, 0); CP_COMMIT();

        const int o0 = tid, o1 = tid + 256;
        const int bA0 = o0 >> 5, jA0 = o0 & 31;
        const int bA1 = o1 >> 5, jA1 = o1 & 31;
        float xg0 = __ldcg(&g_XG[((size_t)((brow0 + bA0) * TS + t)) * G2 + jbaseA + jA0]);
        float xg1 = __ldcg(&g_XG[((size_t)((brow0 + bA1) * TS + t)) * G2 + jbaseA + jA1]);
        unsigned hE0p = 0u, hE1p = 0u;
        if (q < 32) {
            hE0p = __ldcg(&g_h[(brow0 + bA0) * HID + jbaseA + jA0]);
            hE1p = __ldcg(&g_h[(brow0 + bA1) * HID + jbaseA + jA1]);
        }

        float cA[4][4];
#pragma unroll
        for (int i = 0; i < 4; ++i)
#pragma unroll
            for (int j = 0; j < 4; ++j) cA[i][j] = 0.0f;

#pragma unroll
        for (int c = 0; c < 4; ++c) {
            if (c < 3) { issue_chunk(sbase, g_h, brow0, c + 1, (c + 1) & 1); CP_COMMIT(); CP_WAIT(1); }
            else       { CP_WAIT(0); }
            __syncthreads();
            const unsigned* Hb = smem + OFF_HC + (c & 1) * HCBUF;
#pragma unroll
            for (int ki = 0; ki < 4; ++ki) {
                const int kl = warp * 32 + ki * 8 + 2 * tg;   // within-chunk col
                const int kg = c * CK + kl;                   // global k
                uint2 va0 = *(const uint2*)&Hb[(g)     * HSTR + kl];
                uint2 va1 = *(const uint2*)&Hb[(g + 8) * HSTR + kl];
#pragma unroll
                for (int n = 0; n < 4; ++n) {
                    uint2 w = *(const uint2*)&WgS[(n * 8 + g) * WSTRIDE + kg];
                    unsigned p1b0 = __byte_perm(w.x, 0, 0x1010);
                    unsigned p1b1 = __byte_perm(w.y, 0, 0x1010);
                    unsigned p2b0 = w.x >> 16, p2b1 = w.y >> 16;
                    mma_bf16(cA[n], va0.x, va1.x, va0.y, va1.y, p1b0, p1b1);
                    mma_bf16(cA[n], va0.x, va1.x, va0.y, va1.y, p2b0, p2b1);
                }
            }
            __syncthreads();
        }
        // per-warp partials: Red[warp][row*32 + n*8 + 2tg]
#pragma unroll
        for (int n = 0; n < 4; ++n) {
            float* dst = &Red[warp * 512 + g * 32 + n * 8 + 2 * tg];
            *(float2*)dst         = make_float2(cA[n][0], cA[n][1]);
            *(float2*)(dst + 256) = make_float2(cA[n][2], cA[n][3]);   // row g+8
        }
        __syncthreads();
        {
            float s0 = 0.f, s1 = 0.f;
#pragma unroll
            for (int w = 0; w < 8; ++w) { s0 += Red[w * 512 + o0]; s1 += Red[w * 512 + o1]; }
            float sg0 = 1.0f / (1.0f + expf(-(s0 + xg0)));
            float sg1 = 1.0f / (1.0f + expf(-(s1 + xg1)));
            if (q < 32) {
                __stcg(&g_rh[(brow0 + bA0) * HID + jbaseA + jA0], packhl(sg0 * unpackhl(hE0p)));
                __stcg(&g_rh[(brow0 + bA1) * HID + jbaseA + jA1], packhl(sg1 * unpackhl(hE1p)));
            } else {
                __stcg(&g_u[(brow0 + bA0) * HID + (jbaseA - 1024) + jA0], sg0);
                __stcg(&g_u[(brow0 + bA1) * HID + (jbaseA - 1024) + jA1], sg1);
            }
        }
        grid_barrier_h(&bar_target);

        // =================== Phase B: candidate + update ===================
        issue_chunk(sbase, g_rh, brow0, 0, 0); CP_COMMIT();

        const int bB = tid >> 4, jB = tid & 15;
        float xc = __ldcg(&g_XC[((size_t)((brow0 + bB) * TS + t)) * HID + jbaseB + jB]);
        float uv = __ldcg(&g_u[(brow0 + bB) * HID + jbaseB + jB]);
        unsigned hvp = __ldcg(&g_h[(brow0 + bB) * HID + jbaseB + jB]);

        float cB[2][4];
#pragma unroll
        for (int i = 0; i < 2; ++i)
#pragma unroll
            for (int j = 0; j < 4; ++j) cB[i][j] = 0.0f;

#pragma unroll
        for (int c = 0; c < 4; ++c) {
            if (c < 3) { issue_chunk(sbase, g_rh, brow0, c + 1, (c + 1) & 1); CP_COMMIT(); CP_WAIT(1); }
            else       { CP_WAIT(0); }
            __syncthreads();
            const unsigned* Hb = smem + OFF_HC + (c & 1) * HCBUF;
#pragma unroll
            for (int ki = 0; ki < 4; ++ki) {
                const int kl = warp * 32 + ki * 8 + 2 * tg;
                const int kg = c * CK + kl;
                uint2 va0 = *(const uint2*)&Hb[(g)     * HSTR + kl];
                uint2 va1 = *(const uint2*)&Hb[(g + 8) * HSTR + kl];
#pragma unroll
                for (int n = 0; n < 2; ++n) {
                    uint2 w = *(const uint2*)&WcS[(n * 8 + g) * WSTRIDE + kg];
                    unsigned p1b0 = __byte_perm(w.x, 0, 0x1010);
                    unsigned p1b1 = __byte_perm(w.y, 0, 0x1010);
                    unsigned p2b0 = w.x >> 16, p2b1 = w.y >> 16;
                    mma_bf16(cB[n], va0.x, va1.x, va0.y, va1.y, p1b0, p1b1);
                    mma_bf16(cB[n], va0.x, va1.x, va0.y, va1.y, p2b0, p2b1);
                }
            }
            __syncthreads();
        }
#pragma unroll
        for (int n = 0; n < 2; ++n) {
            float* dst = &Red[warp * 256 + g * 16 + n * 8 + 2 * tg];
            *(float2*)dst         = make_float2(cB[n][0], cB[n][1]);
            *(float2*)(dst + 128) = make_float2(cB[n][2], cB[n][3]);   // row g+8
        }
        __syncthreads();
        {
            float s = 0.f;
#pragma unroll
            for (int w = 0; w < 8; ++w) s += Red[w * 256 + tid];
            float cc = tanhf(s + xc);
            float hv = unpackhl(hvp);
            float hn = uv * hv + (1.0f - uv) * cc;
            __stcg(&g_h[(brow0 + bB) * HID + jbaseB + jB], packhl(hn));
            out[((size_t)(brow0 + bB) * TS + t) * HID + jbaseB + jB] = hn;
        }
        grid_barrier_h(&bar_target);
    }
}

// ---------------- launch ----------------
extern "C" void kernel_launch(void* const* d_in, const int* in_sizes, int n_in,
                              void* d_out, int out_size) {
    const float* X  = (const float*)d_in[0];
    const float* gk = (const float*)d_in[1];
    const float* gb = (const float*)d_in[2];
    const float* ck = (const float*)d_in[3];
    const float* cb = (const float*)d_in[4];
    float* out = (float*)d_out;
    (void)in_sizes; (void)n_in; (void)out_size;

    void* pa = nullptr; void* pb = nullptr;
    cudaGetSymbolAddress(&pa, g_XG);
    cudaGetSymbolAddress(&pb, g_XC);
    float* xg_ptr = (float*)pa;
    float* xc_ptr = (float*)pb;

    cudaFuncSetAttribute(gru_recurrent_kernel,
                         cudaFuncAttributeMaxDynamicSharedMemorySize,
                         SMEM_U32 * (int)sizeof(unsigned));

    gru_init_kernel<<<RBLOCKS, 256>>>();
    {
        dim3 grid(G2 / BN, (NB * TS) / BM);
        sgemm_bias_kernel<<<grid, 256>>>(X, gk, gb, xg_ptr, NB * TS, G2, DIN, G2);
    }
    {
        dim3 grid(HID / BN, (NB * TS) / BM);
        sgemm_bias_kernel<<<grid, 256>>>(X, ck, cb, xc_ptr, NB * TS, HID, DIN, HID);
    }
    gru_recurrent_kernel<<<RBLOCKS, RTHREADS, SMEM_U32 * sizeof(unsigned)>>>(gk, ck, out);
}